// round 6
// baseline (speedup 1.0000x reference)
#include <cuda_runtime.h>
#include <cuda_bf16.h>
#include <cstdint>

#define NS     16
#define NC     256
#define D      64
#define NPTS   32768
#define NITER  5
#define TILE_M 128
#define NTILE  (NPTS / TILE_M)   // 256 tiles per space

// ---------------- scratch ----------------
__device__ float          g_c[2][NS * NC * D];
__device__ __nv_bfloat16  g_xh[NS * NPTS * D];
__device__ __nv_bfloat16  g_xl[NS * NPTS * D];
__device__ __nv_bfloat16  g_ch[NS * NC * D];
__device__ __nv_bfloat16  g_cl[NS * NC * D];
__device__ float          g_c2[NS * NC];
__device__ unsigned char  g_assign[NS * NPTS];
__device__ unsigned short g_bucket[NS * NPTS];
__device__ int            g_cnt[NS * NC];
__device__ int            g_off[NS * NC];
__device__ int            g_bh[NS * NTILE * NC];
__device__ int            g_bhoff[NS * NTILE * NC];

#define SW128(off) ((off) ^ (((off) >> 3) & 0x70))

__device__ __forceinline__ uint32_t smem_u32(const void* p) {
    uint32_t a;
    asm("{ .reg .u64 t; cvta.to.shared.u64 t, %1; cvt.u32.u64 %0, t; }"
        : "=r"(a) : "l"(p));
    return a;
}

#define LDSM_X4(r0, r1, r2, r3, addr) \
    asm volatile("ldmatrix.sync.aligned.m8n8.x4.shared.b16 {%0,%1,%2,%3}, [%4];" \
        : "=r"(r0), "=r"(r1), "=r"(r2), "=r"(r3) : "r"(addr))

#define CP16(dst, src) \
    asm volatile("cp.async.cg.shared.global [%0], [%1], 16;" :: "r"(dst), "l"(src))
#define CP_COMMIT() asm volatile("cp.async.commit_group;")
#define CP_WAIT(n)  asm volatile("cp.async.wait_group %0;" :: "n"(n))

__device__ __forceinline__ void mma16816(float* c, const uint32_t* a,
                                         uint32_t b0, uint32_t b1) {
    asm("mma.sync.aligned.m16n8k16.row.col.f32.bf16.bf16.f32 "
        "{%0,%1,%2,%3}, {%4,%5,%6,%7}, {%8,%9}, {%0,%1,%2,%3};"
        : "+f"(c[0]), "+f"(c[1]), "+f"(c[2]), "+f"(c[3])
        : "r"(a[0]), "r"(a[1]), "r"(a[2]), "r"(a[3]), "r"(b0), "r"(b1));
}

__device__ __forceinline__ void top2_ins(float& d1, int& i1, float& d2, int& i2,
                                         float e, int j) {
    if (e < d1 || (e == d1 && j < i1)) { d2 = d1; i2 = i1; d1 = e; i1 = j; }
    else if (e < d2 || (e == d2 && j < i2)) { d2 = e; i2 = j; }
}

// ---------------- init ----------------
__global__ void init_c_kernel(const float* __restrict__ x) {
    int gid = blockIdx.x * blockDim.x + threadIdx.x;
    int d = gid & 63;
    int k = (gid >> 6) & 255;
    int s = gid >> 14;
    g_c[0][gid] = x[((size_t)k * NS + s) * D + d];
}

__global__ void init_xsplit_kernel(const float* __restrict__ x) {
    int gid = blockIdx.x * blockDim.x + threadIdx.x;
    int d = gid & 63;
    int n = (gid >> 6) & (NPTS - 1);
    int s = gid >> 21;
    float v = x[((size_t)n * NS + s) * D + d];
    __nv_bfloat16 h = __float2bfloat16(v);
    __nv_bfloat16 l = __float2bfloat16(v - __bfloat162float(h));
    g_xh[gid] = h;
    g_xl[gid] = l;
}

__global__ void conv_c_kernel(int cur) {
    __shared__ float part[2];
    const int s = blockIdx.y, k = blockIdx.x, t = threadIdx.x;   // t < 64
    size_t idx = ((size_t)s * NC + k) * D + t;
    float v = g_c[cur][idx];
    __nv_bfloat16 h = __float2bfloat16(v);
    __nv_bfloat16 l = __float2bfloat16(v - __bfloat162float(h));
    g_ch[idx] = h;
    g_cl[idx] = l;
    float sq = v * v;
#pragma unroll
    for (int o = 16; o > 0; o >>= 1) sq += __shfl_down_sync(0xffffffffu, sq, o);
    if ((t & 31) == 0) part[t >> 5] = sq;
    __syncthreads();
    if (t == 0) g_c2[s * NC + k] = part[0] + part[1];
}

// ---------------- gemm + argmin ----------------
// smem layout (byte offsets, all 1024-aligned)
#define SM_C2   0                       // 1 KB
#define SM_RED  1024                    // 16 KB
#define SM_AH   17408                   // 16 KB
#define SM_AL   33792                   // 16 KB
#define SM_B0H  50176                   // 16 KB
#define SM_B0L  66560
#define SM_B1H  82944                   // hist aliases here after MMAs
#define SM_B1L  99328
#define SM_TOTAL 115712                 // 113 KB -> 2 CTAs/SM

__global__ __launch_bounds__(256, 2)
void gemm_assign_kernel(const float* __restrict__ x, int cur) {
    extern __shared__ char smem[];
    const uint32_t sb = smem_u32(smem);
    const int tid = threadIdx.x;
    const int wid = tid >> 5, lane = tid & 31;
    const int s = blockIdx.y, tile = blockIdx.x;

    float* c2s  = (float*)(smem + SM_C2);
    float* redf = (float*)(smem + SM_RED);

    // ---- async fills: group0 = A(hi,lo)+B0(hi,lo); group1 = B1(hi,lo) ----
    {
        const uint4* gAh  = (const uint4*)(g_xh + ((size_t)s * NPTS + (size_t)tile * TILE_M) * D);
        const uint4* gAl  = (const uint4*)(g_xl + ((size_t)s * NPTS + (size_t)tile * TILE_M) * D);
        const uint4* gB0h = (const uint4*)(g_ch + (size_t)s * NC * D);
        const uint4* gB0l = (const uint4*)(g_cl + (size_t)s * NC * D);
#pragma unroll
        for (int i = tid; i < TILE_M * 8; i += 256) {
            uint32_t sw = SW128((uint32_t)(i * 16));
            CP16(sb + SM_AH + sw, gAh + i);
            CP16(sb + SM_AL + sw, gAl + i);
            CP16(sb + SM_B0H + sw, gB0h + i);
            CP16(sb + SM_B0L + sw, gB0l + i);
        }
        CP_COMMIT();
        const uint4* gB1h = (const uint4*)(g_ch + ((size_t)s * NC + 128) * D);
        const uint4* gB1l = (const uint4*)(g_cl + ((size_t)s * NC + 128) * D);
#pragma unroll
        for (int i = tid; i < 128 * 8; i += 256) {
            uint32_t sw = SW128((uint32_t)(i * 16));
            CP16(sb + SM_B1H + sw, gB1h + i);
            CP16(sb + SM_B1L + sw, gB1l + i);
        }
        CP_COMMIT();
    }
    c2s[tid] = g_c2[s * NC + tid];

    // ---- warp tiling: 2 (M) x 4 (N); per chunk warp tile 64 x 32 ----
    const int mo = (wid >> 2) * 64;
    const int nwarp = wid & 3;
    const int gq = lane >> 2;
    const int tg = lane & 3;
    const int ac = tg * 2;

    // precomputed swizzled relative addresses; per-ks address = rel ^ (ks*32)
    const int arow_l  = ((lane >> 3) & 1) * 8 + (lane & 7);
    const int akoff_l = (lane >> 4) * 16;
    const int brow_l  = nwarp * 32 + ((lane >> 4) & 1) * 8 + (lane & 7);
    const int bkoff_l = ((lane >> 3) & 1) * 16;

    uint32_t relAH[4], relAL[4];
#pragma unroll
    for (int mf = 0; mf < 4; mf++) {
        int R = mo + mf * 16 + arow_l;
        uint32_t z = (uint32_t)(akoff_l ^ ((R & 7) << 4));
        relAH[mf] = SM_AH + R * 128 + z;
        relAL[mf] = SM_AL + R * 128 + z;
    }
    uint32_t relB[2];
#pragma unroll
    for (int nfp = 0; nfp < 2; nfp++) {
        int R = brow_l + nfp * 16;
        relB[nfp] = R * 128 + (uint32_t)(bkoff_l ^ ((R & 7) << 4));
    }

#pragma unroll
    for (int c = 0; c < 2; c++) {
        if (c == 0) { CP_WAIT(1); } else { CP_WAIT(0); }
        __syncthreads();

        const uint32_t bH = (c == 0) ? SM_B0H : SM_B1H;
        const uint32_t bL = bH + 16384;

        float acc[4][4][4];
#pragma unroll
        for (int mf = 0; mf < 4; mf++)
#pragma unroll
            for (int nf = 0; nf < 4; nf++)
#pragma unroll
                for (int r = 0; r < 4; r++) acc[mf][nf][r] = 0.f;

#pragma unroll
        for (int ks = 0; ks < 4; ks++) {
            const uint32_t kx = (uint32_t)(ks * 32);

            uint32_t aH[4][4];
#pragma unroll
            for (int mf = 0; mf < 4; mf++)
                LDSM_X4(aH[mf][0], aH[mf][1], aH[mf][2], aH[mf][3],
                        sb + (relAH[mf] ^ kx));
            uint32_t bh[2][4];
#pragma unroll
            for (int nfp = 0; nfp < 2; nfp++)
                LDSM_X4(bh[nfp][0], bh[nfp][1], bh[nfp][2], bh[nfp][3],
                        sb + ((bH + relB[nfp]) ^ kx));
            // Ah * Bh
#pragma unroll
            for (int nfp = 0; nfp < 2; nfp++)
#pragma unroll
                for (int mf = 0; mf < 4; mf++) {
                    mma16816(acc[mf][2 * nfp],     aH[mf], bh[nfp][0], bh[nfp][1]);
                    mma16816(acc[mf][2 * nfp + 1], aH[mf], bh[nfp][2], bh[nfp][3]);
                }
            // Ah * Bl
#pragma unroll
            for (int nfp = 0; nfp < 2; nfp++) {
                uint32_t bl[4];
                LDSM_X4(bl[0], bl[1], bl[2], bl[3], sb + ((bL + relB[nfp]) ^ kx));
#pragma unroll
                for (int mf = 0; mf < 4; mf++) {
                    mma16816(acc[mf][2 * nfp],     aH[mf], bl[0], bl[1]);
                    mma16816(acc[mf][2 * nfp + 1], aH[mf], bl[2], bl[3]);
                }
            }
            // Al * Bh
#pragma unroll
            for (int mf = 0; mf < 4; mf++) {
                uint32_t aL[4];
                LDSM_X4(aL[0], aL[1], aL[2], aL[3], sb + (relAL[mf] ^ kx));
#pragma unroll
                for (int nfp = 0; nfp < 2; nfp++) {
                    mma16816(acc[mf][2 * nfp],     aL, bh[nfp][0], bh[nfp][1]);
                    mma16816(acc[mf][2 * nfp + 1], aL, bh[nfp][2], bh[nfp][3]);
                }
            }
        }

        // ---- per-chunk epilogue: top-2 per row over this warp's 32 cols ----
#pragma unroll
        for (int mf = 0; mf < 4; mf++) {
#pragma unroll
            for (int half = 0; half < 2; half++) {
                const int row = mo + mf * 16 + half * 8 + gq;
                float d1 = 3.4e38f, d2 = 3.4e38f;
                int i1 = 0, i2 = 0;
#pragma unroll
                for (int nf = 0; nf < 4; nf++) {
                    const int c0 = c * 128 + nwarp * 32 + nf * 8 + ac;
                    float e0 = __fmaf_rn(-2.f, acc[mf][nf][half * 2],     c2s[c0]);
                    float e1 = __fmaf_rn(-2.f, acc[mf][nf][half * 2 + 1], c2s[c0 + 1]);
                    top2_ins(d1, i1, d2, i2, e0, c0);
                    top2_ins(d1, i1, d2, i2, e1, c0 + 1);
                }
#pragma unroll
                for (int o = 1; o <= 2; o <<= 1) {
                    float od1 = __shfl_xor_sync(0xffffffffu, d1, o);
                    int   oi1 = __shfl_xor_sync(0xffffffffu, i1, o);
                    float od2 = __shfl_xor_sync(0xffffffffu, d2, o);
                    int   oi2 = __shfl_xor_sync(0xffffffffu, i2, o);
                    top2_ins(d1, i1, d2, i2, od1, oi1);
                    top2_ins(d1, i1, d2, i2, od2, oi2);
                }
                if (tg == 0) {
                    float* dst = redf + (row * 8 + c * 4 + nwarp) * 4;
                    dst[0] = d1; ((int*)dst)[1] = i1;
                    dst[2] = d2; ((int*)dst)[3] = i2;
                }
            }
        }
    }

    // hist aliases the B1H buffer (all B reads complete)
    int* hist = (int*)(smem + SM_B1H);
    hist[tid] = 0;
    __syncthreads();

    // ---- final merge + exact fp32 re-rank ----
    if (tid < TILE_M) {
        float d1 = 3.4e38f, d2 = 3.4e38f;
        int i1 = 0, i2 = 0;
#pragma unroll
        for (int sl = 0; sl < 8; sl++) {
            const float* src = redf + (tid * 8 + sl) * 4;
            top2_ins(d1, i1, d2, i2, src[0], ((const int*)src)[1]);
            top2_ins(d1, i1, d2, i2, src[2], ((const int*)src)[3]);
        }
        const int p = tile * TILE_M + tid;
        const int ka = min(i1, i2), kb = max(i1, i2);
        const float4* x4 = (const float4*)(x + ((size_t)p * NS + s) * D);
        const float4* a4 = (const float4*)(g_c[cur] + ((size_t)s * NC + ka) * D);
        const float4* b4 = (const float4*)(g_c[cur] + ((size_t)s * NC + kb) * D);
        float da = 0.f, db = 0.f;
#pragma unroll
        for (int i = 0; i < 16; i++) {
            float4 xv = x4[i], av = a4[i], bv = b4[i];
            da = __fmaf_rn(xv.x, av.x, da); da = __fmaf_rn(xv.y, av.y, da);
            da = __fmaf_rn(xv.z, av.z, da); da = __fmaf_rn(xv.w, av.w, da);
            db = __fmaf_rn(xv.x, bv.x, db); db = __fmaf_rn(xv.y, bv.y, db);
            db = __fmaf_rn(xv.z, bv.z, db); db = __fmaf_rn(xv.w, bv.w, db);
        }
        float dad = __fmaf_rn(-2.f, da, c2s[ka]);
        float dbd = __fmaf_rn(-2.f, db, c2s[kb]);
        int choice = (dbd < dad) ? kb : ka;
        g_assign[s * NPTS + p] = (unsigned char)choice;
        atomicAdd(&hist[choice], 1);
    }
    __syncthreads();

    g_bh[((size_t)s * NTILE + tile) * NC + tid] = hist[tid];
}

// ---------------- scan ----------------
__global__ void scan_kernel() {
    __shared__ int sm[NC];
    const int s = blockIdx.x, k = threadIdx.x;
    int run = 0;
#pragma unroll 4
    for (int b = 0; b < NTILE; b++) {
        size_t idx = ((size_t)s * NTILE + b) * NC + k;
        int v = g_bh[idx];
        g_bhoff[idx] = run;
        run += v;
    }
    g_cnt[s * NC + k] = run;
    sm[k] = run;
    __syncthreads();
    for (int o = 1; o < NC; o <<= 1) {
        int add = (k >= o) ? sm[k - o] : 0;
        __syncthreads();
        sm[k] += add;
        __syncthreads();
    }
    g_off[s * NC + k] = sm[k] - run;
}

// ---------------- scatter ----------------
__global__ void scatter_kernel() {
    __shared__ int warp_hist[4][NC];
    const int s = blockIdx.y, b = blockIdx.x;
    const int tid = threadIdx.x, w = tid >> 5, lane = tid & 31;

    for (int i = tid; i < 4 * NC; i += 128)
        (&warp_hist[0][0])[i] = 0;
    __syncthreads();

    const int p = b * TILE_M + tid;
    const int a = g_assign[s * NPTS + p];

    unsigned mask = __match_any_sync(0xffffffffu, a);
    int lrank  = __popc(mask & ((1u << lane) - 1));
    int leader = __ffs(mask) - 1;
    if (lane == leader) warp_hist[w][a] = __popc(mask);
    __syncthreads();

    int pre = 0;
#pragma unroll
    for (int ww = 0; ww < 4; ww++)
        if (ww < w) pre += warp_hist[ww][a];

    int pos = g_off[s * NC + a]
            + g_bhoff[((size_t)s * NTILE + b) * NC + a]
            + pre + lrank;
    g_bucket[s * NPTS + pos] = (unsigned short)p;
}

// ---------------- update: 4-stream mean + fused split/|c|^2 ----------------
__global__ void update_kernel(const float* __restrict__ x, int cursel,
                              float* __restrict__ outp) {
    __shared__ unsigned short sl[256];
    __shared__ float part[256];
    __shared__ float c2p[2];
    const int s = blockIdx.y, k = blockIdx.x, t = threadIdx.x;  // 256 threads
    const int q = t >> 6, d = t & 63;
    const int base  = s * NC + k;
    const int start = g_off[base];
    const int count = g_cnt[base];

    float acc = 0.f;
    for (int b = 0; b < count; b += 256) {
        int m = min(256, count - b);
        if (t < m) sl[t] = g_bucket[s * NPTS + start + b + t];
        __syncthreads();
        for (int i = q; i < m; i += 4)
            acc += x[((size_t)sl[i] * NS + s) * D + d];
        __syncthreads();
    }
    part[t] = acc;
    __syncthreads();

    if (q == 0) {
        float sum = ((part[d] + part[64 + d]) + (part[128 + d] + part[192 + d]));
        size_t idx = (size_t)base * D + d;
        float res = (count > 0) ? (sum / (float)count) : g_c[cursel][idx];
        float* dst = outp ? outp : g_c[1 - cursel];
        dst[idx] = res;
        __nv_bfloat16 h = __float2bfloat16(res);
        __nv_bfloat16 l = __float2bfloat16(res - __bfloat162float(h));
        g_ch[idx] = h;
        g_cl[idx] = l;
        float sq = res * res;
#pragma unroll
        for (int o = 16; o > 0; o >>= 1) sq += __shfl_down_sync(0xffffffffu, sq, o);
        if ((d & 31) == 0) c2p[d >> 5] = sq;
    }
    __syncthreads();
    if (t == 0) g_c2[base] = c2p[0] + c2p[1];
}

// ---------------- launch ----------------
extern "C" void kernel_launch(void* const* d_in, const int* in_sizes, int n_in,
                              void* d_out, int out_size) {
    const float* x = (const float*)d_in[0];
    float* out = (float*)d_out;

    cudaFuncSetAttribute(gemm_assign_kernel,
                         cudaFuncAttributeMaxDynamicSharedMemorySize, SM_TOTAL);

    init_c_kernel<<<(NS * NC * D) / 256, 256>>>(x);
    init_xsplit_kernel<<<(NS * NPTS * D) / 256, 256>>>(x);
    conv_c_kernel<<<dim3(NC, NS), 64>>>(0);

    int cur = 0;
    for (int it = 0; it < NITER; ++it) {
        gemm_assign_kernel<<<dim3(NTILE, NS), 256, SM_TOTAL>>>(x, cur);
        scan_kernel<<<NS, NC>>>();
        scatter_kernel<<<dim3(NTILE, NS), 128>>>();
        update_kernel<<<dim3(NC, NS), 256>>>(x, cur,
                                             (it == NITER - 1) ? out : nullptr);
        cur ^= 1;
    }
}

// round 7
// speedup vs baseline: 1.4587x; 1.4587x over previous
#include <cuda_runtime.h>
#include <cuda_bf16.h>
#include <cstdint>

#define NS     16
#define NC     256
#define D      64
#define NPTS   32768
#define NITER  5
#define TILE_M 128
#define NTILE  (NPTS / TILE_M)   // 256 tiles per space

// ---------------- scratch ----------------
__device__ float          g_c[2][NS * NC * D];
__device__ __nv_bfloat16  g_xh[NS * NPTS * D];
__device__ __nv_bfloat16  g_xl[NS * NPTS * D];
__device__ __nv_bfloat16  g_ch[NS * NC * D];
__device__ __nv_bfloat16  g_cl[NS * NC * D];
__device__ float          g_c2[NS * NC];
__device__ unsigned char  g_assign[NS * NPTS];
__device__ unsigned short g_bucket[NS * NPTS];
__device__ int            g_cnt[NS * NC];
__device__ int            g_off[NS * NC];
__device__ __align__(16) int g_bh[NS * NC * NTILE];     // [s][k][tile]
__device__ __align__(16) int g_bhoff[NS * NC * NTILE];  // [s][k][tile]

#define SW128(off) ((off) ^ (((off) >> 3) & 0x70))

__device__ __forceinline__ uint32_t smem_u32(const void* p) {
    uint32_t a;
    asm("{ .reg .u64 t; cvta.to.shared.u64 t, %1; cvt.u32.u64 %0, t; }"
        : "=r"(a) : "l"(p));
    return a;
}

#define LDSM_X4(r0, r1, r2, r3, addr) \
    asm volatile("ldmatrix.sync.aligned.m8n8.x4.shared.b16 {%0,%1,%2,%3}, [%4];" \
        : "=r"(r0), "=r"(r1), "=r"(r2), "=r"(r3) : "r"(addr))

#define CP16(dst, src) \
    asm volatile("cp.async.cg.shared.global [%0], [%1], 16;" :: "r"(dst), "l"(src))
#define CP_COMMIT() asm volatile("cp.async.commit_group;")
#define CP_WAIT(n)  asm volatile("cp.async.wait_group %0;" :: "n"(n))

__device__ __forceinline__ void mma16816(float* c, const uint32_t* a,
                                         uint32_t b0, uint32_t b1) {
    asm("mma.sync.aligned.m16n8k16.row.col.f32.bf16.bf16.f32 "
        "{%0,%1,%2,%3}, {%4,%5,%6,%7}, {%8,%9}, {%0,%1,%2,%3};"
        : "+f"(c[0]), "+f"(c[1]), "+f"(c[2]), "+f"(c[3])
        : "r"(a[0]), "r"(a[1]), "r"(a[2]), "r"(a[3]), "r"(b0), "r"(b1));
}

// no-tie-break top-2 insert (deterministic; strict < keeps first occurrence)
__device__ __forceinline__ void top2_nt(float& d1, int& i1, float& d2, int& i2,
                                        float e, int j) {
    bool p1 = e < d1;
    bool p2 = e < d2;
    float nd2 = p1 ? d1 : (p2 ? e : d2);
    int   ni2 = p1 ? i1 : (p2 ? j : i2);
    d1 = p1 ? e : d1;
    i1 = p1 ? j : i1;
    d2 = nd2;
    i2 = ni2;
}

// ---------------- init ----------------
__global__ void init_c_kernel(const float* __restrict__ x) {
    int gid = blockIdx.x * blockDim.x + threadIdx.x;
    int d = gid & 63;
    int k = (gid >> 6) & 255;
    int s = gid >> 14;
    g_c[0][gid] = x[((size_t)k * NS + s) * D + d];
}

__global__ void init_xsplit_kernel(const float* __restrict__ x) {
    int gid = blockIdx.x * blockDim.x + threadIdx.x;
    int d = gid & 63;
    int n = (gid >> 6) & (NPTS - 1);
    int s = gid >> 21;
    float v = x[((size_t)n * NS + s) * D + d];
    __nv_bfloat16 h = __float2bfloat16(v);
    __nv_bfloat16 l = __float2bfloat16(v - __bfloat162float(h));
    g_xh[gid] = h;
    g_xl[gid] = l;
}

__global__ void conv_c_kernel(int cur) {
    __shared__ float part[2];
    const int s = blockIdx.y, k = blockIdx.x, t = threadIdx.x;   // t < 64
    size_t idx = ((size_t)s * NC + k) * D + t;
    float v = g_c[cur][idx];
    __nv_bfloat16 h = __float2bfloat16(v);
    __nv_bfloat16 l = __float2bfloat16(v - __bfloat162float(h));
    g_ch[idx] = h;
    g_cl[idx] = l;
    float sq = v * v;
#pragma unroll
    for (int o = 16; o > 0; o >>= 1) sq += __shfl_down_sync(0xffffffffu, sq, o);
    if ((t & 31) == 0) part[t >> 5] = sq;
    __syncthreads();
    if (t == 0) g_c2[s * NC + k] = part[0] + part[1];
}

// ---------------- gemm + argmin ----------------
// smem layout (byte offsets, all 1024-aligned)
#define SM_C2   0                       // 1 KB
#define SM_RED  1024                    // 16 KB; after merge: cand[128] int2 @0, hist @+1KB
#define SM_AH   17408                   // 16 KB
#define SM_AL   33792                   // 16 KB
#define SM_B0H  50176                   // 16 KB
#define SM_B0L  66560
#define SM_B1H  82944
#define SM_B1L  99328
#define SM_TOTAL 115712                 // 113 KB -> 2 CTAs/SM

__global__ __launch_bounds__(256, 2)
void gemm_assign_kernel(const float* __restrict__ x, int cur) {
    extern __shared__ char smem[];
    const uint32_t sb = smem_u32(smem);
    const int tid = threadIdx.x;
    const int wid = tid >> 5, lane = tid & 31;
    const int s = blockIdx.y, tile = blockIdx.x;

    float* c2s  = (float*)(smem + SM_C2);
    float* redf = (float*)(smem + SM_RED);

    // ---- async fills: group0 = A(hi,lo)+B0(hi,lo); group1 = B1(hi,lo) ----
    {
        const uint4* gAh  = (const uint4*)(g_xh + ((size_t)s * NPTS + (size_t)tile * TILE_M) * D);
        const uint4* gAl  = (const uint4*)(g_xl + ((size_t)s * NPTS + (size_t)tile * TILE_M) * D);
        const uint4* gB0h = (const uint4*)(g_ch + (size_t)s * NC * D);
        const uint4* gB0l = (const uint4*)(g_cl + (size_t)s * NC * D);
#pragma unroll
        for (int i = tid; i < TILE_M * 8; i += 256) {
            uint32_t sw = SW128((uint32_t)(i * 16));
            CP16(sb + SM_AH + sw, gAh + i);
            CP16(sb + SM_AL + sw, gAl + i);
            CP16(sb + SM_B0H + sw, gB0h + i);
            CP16(sb + SM_B0L + sw, gB0l + i);
        }
        CP_COMMIT();
        const uint4* gB1h = (const uint4*)(g_ch + ((size_t)s * NC + 128) * D);
        const uint4* gB1l = (const uint4*)(g_cl + ((size_t)s * NC + 128) * D);
#pragma unroll
        for (int i = tid; i < 128 * 8; i += 256) {
            uint32_t sw = SW128((uint32_t)(i * 16));
            CP16(sb + SM_B1H + sw, gB1h + i);
            CP16(sb + SM_B1L + sw, gB1l + i);
        }
        CP_COMMIT();
    }
    c2s[tid] = g_c2[s * NC + tid];

    // ---- warp tiling: 2 (M) x 4 (N); per chunk warp tile 64 x 32 ----
    const int mo = (wid >> 2) * 64;
    const int nwarp = wid & 3;
    const int gq = lane >> 2;
    const int tg = lane & 3;
    const int ac = tg * 2;

    const int arow_l  = ((lane >> 3) & 1) * 8 + (lane & 7);
    const int akoff_l = (lane >> 4) * 16;
    const int brow_l  = nwarp * 32 + ((lane >> 4) & 1) * 8 + (lane & 7);
    const int bkoff_l = ((lane >> 3) & 1) * 16;

    uint32_t relAH[4], relAL[4];
#pragma unroll
    for (int mf = 0; mf < 4; mf++) {
        int R = mo + mf * 16 + arow_l;
        uint32_t z = (uint32_t)(akoff_l ^ ((R & 7) << 4));
        relAH[mf] = SM_AH + R * 128 + z;
        relAL[mf] = SM_AL + R * 128 + z;
    }
    uint32_t relB[2];
#pragma unroll
    for (int nfp = 0; nfp < 2; nfp++) {
        int R = brow_l + nfp * 16;
        relB[nfp] = R * 128 + (uint32_t)(bkoff_l ^ ((R & 7) << 4));
    }

#pragma unroll
    for (int c = 0; c < 2; c++) {
        if (c == 0) { CP_WAIT(1); } else { CP_WAIT(0); }
        __syncthreads();

        const uint32_t bH = (c == 0) ? SM_B0H : SM_B1H;
        const uint32_t bL = bH + 16384;

        float acc[4][4][4];
#pragma unroll
        for (int mf = 0; mf < 4; mf++)
#pragma unroll
            for (int nf = 0; nf < 4; nf++)
#pragma unroll
                for (int r = 0; r < 4; r++) acc[mf][nf][r] = 0.f;

#pragma unroll
        for (int ks = 0; ks < 4; ks++) {
            const uint32_t kx = (uint32_t)(ks * 32);

            uint32_t aH[4][4];
#pragma unroll
            for (int mf = 0; mf < 4; mf++)
                LDSM_X4(aH[mf][0], aH[mf][1], aH[mf][2], aH[mf][3],
                        sb + (relAH[mf] ^ kx));
            uint32_t bh[2][4];
#pragma unroll
            for (int nfp = 0; nfp < 2; nfp++)
                LDSM_X4(bh[nfp][0], bh[nfp][1], bh[nfp][2], bh[nfp][3],
                        sb + ((bH + relB[nfp]) ^ kx));
            // Ah * Bh
#pragma unroll
            for (int nfp = 0; nfp < 2; nfp++)
#pragma unroll
                for (int mf = 0; mf < 4; mf++) {
                    mma16816(acc[mf][2 * nfp],     aH[mf], bh[nfp][0], bh[nfp][1]);
                    mma16816(acc[mf][2 * nfp + 1], aH[mf], bh[nfp][2], bh[nfp][3]);
                }
            // Ah * Bl
#pragma unroll
            for (int nfp = 0; nfp < 2; nfp++) {
                uint32_t bl[4];
                LDSM_X4(bl[0], bl[1], bl[2], bl[3], sb + ((bL + relB[nfp]) ^ kx));
#pragma unroll
                for (int mf = 0; mf < 4; mf++) {
                    mma16816(acc[mf][2 * nfp],     aH[mf], bl[0], bl[1]);
                    mma16816(acc[mf][2 * nfp + 1], aH[mf], bl[2], bl[3]);
                }
            }
            // Al * Bh
#pragma unroll
            for (int mf = 0; mf < 4; mf++) {
                uint32_t aL[4];
                LDSM_X4(aL[0], aL[1], aL[2], aL[3], sb + (relAL[mf] ^ kx));
#pragma unroll
                for (int nfp = 0; nfp < 2; nfp++) {
                    mma16816(acc[mf][2 * nfp],     aL, bh[nfp][0], bh[nfp][1]);
                    mma16816(acc[mf][2 * nfp + 1], aL, bh[nfp][2], bh[nfp][3]);
                }
            }
        }

        // ---- per-chunk epilogue: dual-chain top-2 per row over 32 cols ----
#pragma unroll
        for (int mf = 0; mf < 4; mf++) {
#pragma unroll
            for (int half = 0; half < 2; half++) {
                const int row = mo + mf * 16 + half * 8 + gq;
                float d1e = 3.4e38f, d2e = 3.4e38f, d1o = 3.4e38f, d2o = 3.4e38f;
                int i1e = 0, i2e = 0, i1o = 0, i2o = 0;
#pragma unroll
                for (int nf = 0; nf < 4; nf++) {
                    const int c0 = c * 128 + nwarp * 32 + nf * 8 + ac;
                    float e0 = __fmaf_rn(-2.f, acc[mf][nf][half * 2],     c2s[c0]);
                    float e1 = __fmaf_rn(-2.f, acc[mf][nf][half * 2 + 1], c2s[c0 + 1]);
                    top2_nt(d1e, i1e, d2e, i2e, e0, c0);
                    top2_nt(d1o, i1o, d2o, i2o, e1, c0 + 1);
                }
                top2_nt(d1e, i1e, d2e, i2e, d1o, i1o);
                top2_nt(d1e, i1e, d2e, i2e, d2o, i2o);
#pragma unroll
                for (int o = 1; o <= 2; o <<= 1) {
                    float od1 = __shfl_xor_sync(0xffffffffu, d1e, o);
                    int   oi1 = __shfl_xor_sync(0xffffffffu, i1e, o);
                    float od2 = __shfl_xor_sync(0xffffffffu, d2e, o);
                    int   oi2 = __shfl_xor_sync(0xffffffffu, i2e, o);
                    top2_nt(d1e, i1e, d2e, i2e, od1, oi1);
                    top2_nt(d1e, i1e, d2e, i2e, od2, oi2);
                }
                if (tg == 0) {
                    float* dst = redf + (row * 8 + c * 4 + nwarp) * 4;
                    dst[0] = d1e; ((int*)dst)[1] = i1e;
                    dst[2] = d2e; ((int*)dst)[3] = i2e;
                }
            }
        }
    }
    __syncthreads();

    // ---- final per-row merge (tid<128) ----
    int ka = 0, kb = 0;
    if (tid < TILE_M) {
        float d1 = 3.4e38f, d2 = 3.4e38f;
        int i1 = 0, i2 = 0;
#pragma unroll
        for (int sl = 0; sl < 8; sl++) {
            const float* src = redf + (tid * 8 + sl) * 4;
            top2_nt(d1, i1, d2, i2, src[0], ((const int*)src)[1]);
            top2_nt(d1, i1, d2, i2, src[2], ((const int*)src)[3]);
        }
        ka = min(i1, i2); kb = max(i1, i2);
    }
    __syncthreads();   // all redf reads done; region reusable

    int2* cand = (int2*)(smem + SM_RED);           // 128 * 8 B
    int*  hist = (int*)(smem + SM_RED + 1024);     // 256 * 4 B
    if (tid < TILE_M) cand[tid] = make_int2(ka, kb);
    hist[tid] = 0;
    __syncthreads();

    // ---- split exact fp32 re-rank: 2 threads per point ----
    {
        const int pl   = tid >> 1;          // local point 0..127
        const int half = tid & 1;
        const int2 cd  = cand[pl];
        const int  k0  = half ? cd.y : cd.x;
        const int  p   = tile * TILE_M + pl;
        const float4* x4 = (const float4*)(x + ((size_t)p * NS + s) * D);
        const float4* c4 = (const float4*)(g_c[cur] + ((size_t)s * NC + k0) * D);
        float da = 0.f, db = 0.f;
#pragma unroll
        for (int i = 0; i < 16; i += 2) {
            float4 xv = x4[i], cv = c4[i];
            da = __fmaf_rn(xv.x, cv.x, da); da = __fmaf_rn(xv.y, cv.y, da);
            da = __fmaf_rn(xv.z, cv.z, da); da = __fmaf_rn(xv.w, cv.w, da);
            float4 xw = x4[i + 1], cw = c4[i + 1];
            db = __fmaf_rn(xw.x, cw.x, db); db = __fmaf_rn(xw.y, cw.y, db);
            db = __fmaf_rn(xw.z, cw.z, db); db = __fmaf_rn(xw.w, cw.w, db);
        }
        float dist = __fmaf_rn(-2.f, da + db, c2s[k0]);
        float odist = __shfl_xor_sync(0xffffffffu, dist, 1);
        if (half == 0) {
            // partner (half==1) evaluated cd.y=kb; strict < -> prefer ka on tie
            int choice = (odist < dist) ? cd.y : cd.x;
            g_assign[s * NPTS + p] = (unsigned char)choice;
            atomicAdd(&hist[choice], 1);
        }
    }
    __syncthreads();

    g_bh[((size_t)s * NC + tid) * NTILE + tile] = hist[tid];
}

// ---------------- scan: vectorized per-k prefix + cross-k exclusive scan ----------------
__global__ void scan_kernel() {
    __shared__ int sm[NC];
    const int s = blockIdx.x, k = threadIdx.x;
    const int4* src = (const int4*)(g_bh + ((size_t)s * NC + k) * NTILE);
    int4*       dst = (int4*)(g_bhoff + ((size_t)s * NC + k) * NTILE);
    int run = 0;
#pragma unroll 4
    for (int b = 0; b < NTILE / 4; b++) {
        int4 v = src[b];
        int4 o;
        o.x = run; run += v.x;
        o.y = run; run += v.y;
        o.z = run; run += v.z;
        o.w = run; run += v.w;
        dst[b] = o;
    }
    g_cnt[s * NC + k] = run;
    sm[k] = run;
    __syncthreads();
    for (int o = 1; o < NC; o <<= 1) {
        int add = (k >= o) ? sm[k - o] : 0;
        __syncthreads();
        sm[k] += add;
        __syncthreads();
    }
    g_off[s * NC + k] = sm[k] - run;
}

// ---------------- scatter ----------------
__global__ void scatter_kernel() {
    __shared__ int warp_hist[4][NC];
    const int s = blockIdx.y, b = blockIdx.x;
    const int tid = threadIdx.x, w = tid >> 5, lane = tid & 31;

    for (int i = tid; i < 4 * NC; i += 128)
        (&warp_hist[0][0])[i] = 0;
    __syncthreads();

    const int p = b * TILE_M + tid;
    const int a = g_assign[s * NPTS + p];

    unsigned mask = __match_any_sync(0xffffffffu, a);
    int lrank  = __popc(mask & ((1u << lane) - 1));
    int leader = __ffs(mask) - 1;
    if (lane == leader) warp_hist[w][a] = __popc(mask);
    __syncthreads();

    int pre = 0;
#pragma unroll
    for (int ww = 0; ww < 4; ww++)
        if (ww < w) pre += warp_hist[ww][a];

    int pos = g_off[s * NC + a]
            + g_bhoff[((size_t)s * NC + a) * NTILE + b]
            + pre + lrank;
    g_bucket[s * NPTS + pos] = (unsigned short)p;
}

// ---------------- update: dual-stream mean + fused split/|c|^2 ----------------
__global__ void update_kernel(const float* __restrict__ x, int cursel,
                              float* __restrict__ outp) {
    __shared__ unsigned short sl[256];
    __shared__ float part[256];
    __shared__ float c2p[2];
    const int s = blockIdx.y, k = blockIdx.x, t = threadIdx.x;  // 256 threads
    const int q = t >> 6, d = t & 63;
    const int base  = s * NC + k;
    const int start = g_off[base];
    const int count = g_cnt[base];

    float acc0 = 0.f, acc1 = 0.f;
    for (int b = 0; b < count; b += 256) {
        int m = min(256, count - b);
        if (t < m) sl[t] = g_bucket[s * NPTS + start + b + t];
        __syncthreads();
        int i = q;
        for (; i + 4 < m; i += 8) {
            acc0 += x[((size_t)sl[i] * NS + s) * D + d];
            acc1 += x[((size_t)sl[i + 4] * NS + s) * D + d];
        }
        if (i < m) acc0 += x[((size_t)sl[i] * NS + s) * D + d];
        __syncthreads();
    }
    part[t] = acc0 + acc1;
    __syncthreads();

    if (q == 0) {
        float sum = ((part[d] + part[64 + d]) + (part[128 + d] + part[192 + d]));
        size_t idx = (size_t)base * D + d;
        float res = (count > 0) ? (sum / (float)count) : g_c[cursel][idx];
        float* dst = outp ? outp : g_c[1 - cursel];
        dst[idx] = res;
        __nv_bfloat16 h = __float2bfloat16(res);
        __nv_bfloat16 l = __float2bfloat16(res - __bfloat162float(h));
        g_ch[idx] = h;
        g_cl[idx] = l;
        float sq = res * res;
#pragma unroll
        for (int o = 16; o > 0; o >>= 1) sq += __shfl_down_sync(0xffffffffu, sq, o);
        if ((d & 31) == 0) c2p[d >> 5] = sq;
    }
    __syncthreads();
    if (t == 0) g_c2[base] = c2p[0] + c2p[1];
}

// ---------------- launch ----------------
extern "C" void kernel_launch(void* const* d_in, const int* in_sizes, int n_in,
                              void* d_out, int out_size) {
    const float* x = (const float*)d_in[0];
    float* out = (float*)d_out;

    cudaFuncSetAttribute(gemm_assign_kernel,
                         cudaFuncAttributeMaxDynamicSharedMemorySize, SM_TOTAL);

    init_c_kernel<<<(NS * NC * D) / 256, 256>>>(x);
    init_xsplit_kernel<<<(NS * NPTS * D) / 256, 256>>>(x);
    conv_c_kernel<<<dim3(NC, NS), 64>>>(0);

    int cur = 0;
    for (int it = 0; it < NITER; ++it) {
        gemm_assign_kernel<<<dim3(NTILE, NS), 256, SM_TOTAL>>>(x, cur);
        scan_kernel<<<NS, NC>>>();
        scatter_kernel<<<dim3(NTILE, NS), 128>>>();
        update_kernel<<<dim3(NC, NS), 256>>>(x, cur,
                                             (it == NITER - 1) ? out : nullptr);
        cur ^= 1;
    }
}